// round 1
// baseline (speedup 1.0000x reference)
#include <cuda_runtime.h>
#include <cuda_bf16.h>

// Problem constants
#define BATCH 32
#define HW 56
#define EMB 256
#define NHEAD 8
#define HDIM 32
#define NWIN 64
#define WS 7
#define SSH 3
#define WD 49   // tokens per window
#define NPOS 3136  // 56*56

// Scratch: attention output, laid out in final (un-shifted) token order.
// (B, H*W, E) fp32 = 411 MB static device array (allocation-free rule).
__device__ float g_Y[(size_t)BATCH * NPOS * EMB];

// ---------------------------------------------------------------------------
// Kernel A: fused shifted-window attention per (batch, window, head).
// grid = 32*64*8 = 16384 blocks, 128 threads.
// ---------------------------------------------------------------------------
__global__ __launch_bounds__(128) void swmsa_attn_kernel(
    const float* __restrict__ x,      // (B, 3136, 256)
    const float* __restrict__ qkv_w,  // (32, 96)
    const float* __restrict__ qkv_b,  // (96,)
    const float* __restrict__ rpb)    // (169, 8)
{
    const int blk = blockIdx.x;
    const int h   = blk & (NHEAD - 1);
    const int w   = (blk >> 3) & (NWIN - 1);
    const int b   = blk >> 9;
    const int t   = threadIdx.x;

    __shared__ float xh[WD][HDIM];      // 49x32 input slice
    __shared__ float w_s[HDIM][96];     // qkv weight
    __shared__ float b_s[96];
    __shared__ float q_s[WD][HDIM];
    __shared__ float k_s[WD][HDIM];
    __shared__ float v_s[WD][HDIM];
    __shared__ float s_s[WD][WD];       // scores / attn
    __shared__ float rpb_s[169];
    __shared__ int   pos_s[WD];         // original token position (row*56+col)
    __shared__ int   reg_s[WD];         // shift-mask region id

    const int wi = w >> 3, wj = w & 7;

    if (t < WD) {
        int a = t / 7, c = t % 7;
        int hh = wi * 7 + a;            // coordinate in SHIFTED image
        int ww = wj * 7 + c;
        int row = hh + SSH; if (row >= HW) row -= HW;  // back to original coords
        int col = ww + SSH; if (col >= HW) col -= HW;
        pos_s[t] = row * HW + col;
        int fh = hh < HW - WS ? 0 : (hh < HW - SSH ? 1 : 2);
        int fw = ww < HW - WS ? 0 : (ww < HW - SSH ? 1 : 2);
        reg_s[t] = fh * 3 + fw;
    }
    for (int i = t; i < 169; i += 128) rpb_s[i] = rpb[i * NHEAD + h];
    for (int i = t; i < HDIM * 96; i += 128) (&w_s[0][0])[i] = qkv_w[i];
    if (t < 96) b_s[t] = qkv_b[t];
    __syncthreads();

    // Load x slice for this head: 49 tokens x 32 dims (128B contiguous per token)
    const float* xb = x + ((size_t)b * NPOS) * EMB + h * HDIM;
    for (int i = t; i < WD * HDIM; i += 128) {
        int tok = i >> 5, d = i & 31;
        xh[tok][d] = xb[(size_t)pos_s[tok] * EMB + d];
    }
    __syncthreads();

    // --- QKV projection: thread j computes output column j for all 49 rows ---
    if (t < 96) {
        float wcol[HDIM];
        #pragma unroll
        for (int kk = 0; kk < HDIM; kk++) wcol[kk] = w_s[kk][t];
        const float bias = b_s[t];
        const int sec = t >> 5;        // 0=q, 1=k, 2=v
        const int d = t & 31;
        const float scl = (sec == 0) ? 0.17677669529663688f : 1.0f; // 1/sqrt(32) folded into q
        float* dst = (sec == 0) ? &q_s[0][0] : (sec == 1) ? &k_s[0][0] : &v_s[0][0];
        #pragma unroll 7
        for (int r = 0; r < WD; r++) {
            float acc = bias;
            #pragma unroll
            for (int kk = 0; kk < HDIM; kk++) acc += xh[r][kk] * wcol[kk];
            dst[r * HDIM + d] = acc * scl;
        }
    }
    __syncthreads();

    // --- Scores: thread (q, half) computes 24-25 of the 49 columns ---
    if (t < 98) {
        const int q = t >> 1, half = t & 1;
        float qreg[HDIM];
        #pragma unroll
        for (int kk = 0; kk < HDIM; kk++) qreg[kk] = q_s[q][kk];
        const int aq = q / 7, bq = q % 7;
        const int rq = reg_s[q];
        const int k0 = half * 25, k1 = half ? WD : 25;
        for (int k = k0; k < k1; k++) {
            float acc = 0.0f;
            #pragma unroll
            for (int kk = 0; kk < HDIM; kk++) acc += qreg[kk] * k_s[k][kk];
            int ak = k / 7, bk = k % 7;
            acc += rpb_s[(aq - ak + WS - 1) * (2 * WS - 1) + (bq - bk + WS - 1)];
            if (reg_s[k] != rq) acc -= 100.0f;
            s_s[q][k] = acc;
        }
    }
    __syncthreads();

    // --- Softmax: warp per row, lanes cover the 49 columns ---
    {
        const int warp = t >> 5, lane = t & 31;
        for (int r = warp; r < WD; r += 4) {
            float v0 = s_s[r][lane];
            float v1 = (lane + 32 < WD) ? s_s[r][lane + 32] : -1e30f;
            float m = fmaxf(v0, v1);
            #pragma unroll
            for (int o = 16; o; o >>= 1) m = fmaxf(m, __shfl_xor_sync(~0u, m, o));
            float e0 = __expf(v0 - m);
            float e1 = (lane + 32 < WD) ? __expf(v1 - m) : 0.0f;
            float s = e0 + e1;
            #pragma unroll
            for (int o = 16; o; o >>= 1) s += __shfl_xor_sync(~0u, s, o);
            float inv = 1.0f / s;
            s_s[r][lane] = e0 * inv;
            if (lane + 32 < WD) s_s[r][lane + 32] = e1 * inv;
        }
    }
    __syncthreads();

    // --- O = attn @ V, scatter-store to un-shifted layout ---
    {
        const int d = t & 31, qg = t >> 5;
        float* Yb = g_Y + ((size_t)b * NPOS) * EMB + h * HDIM + d;
        for (int q = qg; q < WD; q += 4) {
            float acc = 0.0f;
            #pragma unroll 7
            for (int k = 0; k < WD; k++) acc += s_s[q][k] * v_s[k][d];
            Yb[(size_t)pos_s[q] * EMB] = acc;
        }
    }
}

// ---------------------------------------------------------------------------
// Kernel B: out = Y @ proj_w + proj_b   (M=100352, N=256, K=256) fp32 SGEMM
// block tile 128x64, thread tile 8x4, BK=16, 256 threads.
// ---------------------------------------------------------------------------
__global__ __launch_bounds__(256) void swmsa_proj_kernel(
    const float* __restrict__ Wg,     // proj_w (256, 256)
    const float* __restrict__ bg,     // proj_b (256,)
    float* __restrict__ out)          // (B*3136, 256)
{
    const int t = threadIdx.x;
    const int tx = t & 15;            // 16 col-groups of 4
    const int ty = t >> 4;            // 16 row-groups of 8
    const int n0 = blockIdx.x * 64;
    const int m0 = blockIdx.y * 128;

    __shared__ float As[16][128];     // [k][m] transposed
    __shared__ float Bs[16][64];      // [k][n]

    float acc[8][4];
    #pragma unroll
    for (int i = 0; i < 8; i++)
        #pragma unroll
        for (int j = 0; j < 4; j++) acc[i][j] = 0.0f;

    const float* Ybase = g_Y + (size_t)m0 * EMB;

    for (int kt = 0; kt < 16; kt++) {
        // load A tile 128x16 (transposed into smem)
        {
            int f = t * 2;
            #pragma unroll
            for (int i = 0; i < 2; i++, f++) {
                int m = f >> 2, kq = (f & 3) * 4;
                float4 av = *(const float4*)(Ybase + (size_t)m * EMB + kt * 16 + kq);
                As[kq + 0][m] = av.x;
                As[kq + 1][m] = av.y;
                As[kq + 2][m] = av.z;
                As[kq + 3][m] = av.w;
            }
        }
        // load B tile 16x64
        {
            int kr = t >> 4, c4 = (t & 15) * 4;
            *(float4*)&Bs[kr][c4] =
                *(const float4*)(Wg + (size_t)(kt * 16 + kr) * EMB + n0 + c4);
        }
        __syncthreads();

        #pragma unroll
        for (int kk = 0; kk < 16; kk++) {
            float4 a0 = *(float4*)&As[kk][ty * 8];
            float4 a1 = *(float4*)&As[kk][ty * 8 + 4];
            float4 bv = *(float4*)&Bs[kk][tx * 4];
            float ar[8] = {a0.x, a0.y, a0.z, a0.w, a1.x, a1.y, a1.z, a1.w};
            float br[4] = {bv.x, bv.y, bv.z, bv.w};
            #pragma unroll
            for (int i = 0; i < 8; i++)
                #pragma unroll
                for (int j = 0; j < 4; j++) acc[i][j] += ar[i] * br[j];
        }
        __syncthreads();
    }

    float4 bb = *(const float4*)(bg + n0 + tx * 4);
    #pragma unroll
    for (int i = 0; i < 8; i++) {
        int row = m0 + ty * 8 + i;
        float4 o;
        o.x = acc[i][0] + bb.x;
        o.y = acc[i][1] + bb.y;
        o.z = acc[i][2] + bb.z;
        o.w = acc[i][3] + bb.w;
        *(float4*)(out + (size_t)row * EMB + n0 + tx * 4) = o;
    }
}

extern "C" void kernel_launch(void* const* d_in, const int* in_sizes, int n_in,
                              void* d_out, int out_size)
{
    const float* x      = (const float*)d_in[0];
    const float* qkv_w  = (const float*)d_in[1];
    const float* qkv_b  = (const float*)d_in[2];
    const float* proj_w = (const float*)d_in[3];
    const float* proj_b = (const float*)d_in[4];
    const float* rpb    = (const float*)d_in[5];
    float* out = (float*)d_out;

    swmsa_attn_kernel<<<BATCH * NWIN * NHEAD, 128>>>(x, qkv_w, qkv_b, rpb);
    swmsa_proj_kernel<<<dim3(256 / 64, (BATCH * NPOS) / 128), 256>>>(proj_w, proj_b, out);
}

// round 2
// speedup vs baseline: 1.3478x; 1.3478x over previous
#include <cuda_runtime.h>
#include <cuda_bf16.h>

#define BATCH 32
#define HW 56
#define EMB 256
#define NHEAD 8
#define HDIM 32
#define NWIN 64
#define WS 7
#define SSH 3
#define WD 49
#define NPOS 3136
#define NBLK (BATCH * NWIN * NHEAD)   // 16384
#define HSL (WD * HDIM)               // 1568 floats per (b,w,h) slice

// Scratch (allocation-free rule: static device arrays)
__device__ float g_Q[(size_t)NBLK * HSL];
__device__ float g_K[(size_t)NBLK * HSL];
__device__ float g_V[(size_t)NBLK * HSL];
__device__ float g_Y[(size_t)BATCH * NPOS * EMB];

// ---------------------------------------------------------------------------
// helpers: token position & shift-mask region for window w, token t
// ---------------------------------------------------------------------------
__device__ __forceinline__ void win_token(int w, int t, int& pos, int& reg)
{
    const int wi = w >> 3, wj = w & 7;
    int a = t / 7, c = t % 7;
    int hh = wi * 7 + a;                 // coordinate in SHIFTED image
    int ww = wj * 7 + c;
    int row = hh + SSH; if (row >= HW) row -= HW;   // original coords
    int col = ww + SSH; if (col >= HW) col -= HW;
    pos = row * HW + col;
    int fh = hh < HW - WS ? 0 : (hh < HW - SSH ? 1 : 2);
    int fw = ww < HW - WS ? 0 : (ww < HW - SSH ? 1 : 2);
    reg = fh * 3 + fw;
}

// ---------------------------------------------------------------------------
// Kernel 1: per-token QKV, written in window-gathered order.
// grid = 16384 (b,w,h) blocks, 96 threads (one per output column of q|k|v).
// ---------------------------------------------------------------------------
__global__ __launch_bounds__(96) void qkv_kernel(
    const float* __restrict__ x,      // (B,3136,256)
    const float* __restrict__ qkv_w,  // (32,96)
    const float* __restrict__ qkv_b)  // (96,)
{
    const int blk = blockIdx.x;
    const int h   = blk & (NHEAD - 1);
    const int w   = (blk >> 3) & (NWIN - 1);
    const int b   = blk >> 9;
    const int t   = threadIdx.x;

    __shared__ float xh[WD][HDIM];
    __shared__ int   pos_s[WD];

    if (t < WD) { int p, r; win_token(w, t, p, r); pos_s[t] = p; }
    __syncthreads();

    const float* xb = x + ((size_t)b * NPOS) * EMB + h * HDIM;
    for (int i = t; i < WD * HDIM; i += 96) {
        int tok = i >> 5, d = i & 31;
        xh[tok][d] = xb[(size_t)pos_s[tok] * EMB + d];
    }

    // weight column for this output (coalesced per kk)
    float wcol[HDIM];
    #pragma unroll
    for (int kk = 0; kk < HDIM; kk++) wcol[kk] = __ldg(&qkv_w[kk * 96 + t]);
    const float bias = __ldg(&qkv_b[t]);
    const int sec = t >> 5, d = t & 31;
    const float scl = (sec == 0) ? 0.17677669529663688f : 1.0f;  // 1/sqrt(32) into q
    float* dst = (sec == 0 ? g_Q : sec == 1 ? g_K : g_V) + (size_t)blk * HSL + d;
    __syncthreads();

    #pragma unroll 7
    for (int r = 0; r < WD; r++) {
        float acc = bias;
        const float4* xr = (const float4*)&xh[r][0];
        #pragma unroll
        for (int j = 0; j < 8; j++) {
            float4 xv = xr[j];
            acc += xv.x * wcol[j*4+0] + xv.y * wcol[j*4+1]
                 + xv.z * wcol[j*4+2] + xv.w * wcol[j*4+3];
        }
        dst[r * HDIM] = acc * scl;
    }
}

// ---------------------------------------------------------------------------
// Kernel 2: windowed attention per (b,w,h). 128 threads.
// ---------------------------------------------------------------------------
__global__ __launch_bounds__(128) void attn_kernel(
    const float* __restrict__ rpb)    // (169, 8)
{
    const int blk = blockIdx.x;
    const int h   = blk & (NHEAD - 1);
    const int w   = (blk >> 3) & (NWIN - 1);
    const int b   = blk >> 9;
    const int t   = threadIdx.x;

    __shared__ float k_s[WD][HDIM];
    __shared__ float v_s[WD][HDIM];
    __shared__ float s_s[WD][WD];
    __shared__ float rpb_s[169];
    __shared__ int   pos_s[WD];
    __shared__ int   reg_s[WD];

    if (t < WD) { int p, r; win_token(w, t, p, r); pos_s[t] = p; reg_s[t] = r; }
    for (int i = t; i < 169; i += 128) rpb_s[i] = rpb[i * NHEAD + h];

    const size_t base = (size_t)blk * HSL;
    {
        const float4* gk = (const float4*)(g_K + base);
        const float4* gv = (const float4*)(g_V + base);
        float4* ks4 = (float4*)&k_s[0][0];
        float4* vs4 = (float4*)&v_s[0][0];
        for (int i = t; i < HSL / 4; i += 128) { ks4[i] = gk[i]; vs4[i] = gv[i]; }
    }
    __syncthreads();

    // --- scores: thread (q, half) covers 25/24 columns, q in registers ---
    if (t < 2 * WD) {
        const int q = t >> 1, half = t & 1;
        float4 qreg[8];
        const float4* gq = (const float4*)(g_Q + base + (size_t)q * HDIM);
        #pragma unroll
        for (int j = 0; j < 8; j++) qreg[j] = gq[j];
        const int aq = q / 7, bq = q % 7;
        const int rq = reg_s[q];
        const int k0 = half * 25, k1 = half ? WD : 25;
        for (int k = k0; k < k1; k++) {
            const float4* kr = (const float4*)&k_s[k][0];
            float acc = 0.0f;
            #pragma unroll
            for (int j = 0; j < 8; j++) {
                float4 kv = kr[j];
                acc += qreg[j].x * kv.x + qreg[j].y * kv.y
                     + qreg[j].z * kv.z + qreg[j].w * kv.w;
            }
            int ak = k / 7, bk = k % 7;
            acc += rpb_s[(aq - ak + WS - 1) * (2 * WS - 1) + (bq - bk + WS - 1)];
            if (reg_s[k] != rq) acc -= 100.0f;
            s_s[q][k] = acc;
        }
    }
    __syncthreads();

    // --- softmax: warp per row ---
    {
        const int warp = t >> 5, lane = t & 31;
        for (int r = warp; r < WD; r += 4) {
            float v0 = s_s[r][lane];
            float v1 = (lane + 32 < WD) ? s_s[r][lane + 32] : -1e30f;
            float m = fmaxf(v0, v1);
            #pragma unroll
            for (int o = 16; o; o >>= 1) m = fmaxf(m, __shfl_xor_sync(~0u, m, o));
            float e0 = __expf(v0 - m);
            float e1 = (lane + 32 < WD) ? __expf(v1 - m) : 0.0f;
            float s = e0 + e1;
            #pragma unroll
            for (int o = 16; o; o >>= 1) s += __shfl_xor_sync(~0u, s, o);
            float inv = 1.0f / s;
            s_s[r][lane] = e0 * inv;
            if (lane + 32 < WD) s_s[r][lane + 32] = e1 * inv;
        }
    }
    __syncthreads();

    // --- O = attn @ V: blocked 4q x 4d per thread (low LDS/FMA ratio) ---
    {
        const int dg = t & 7;       // 8 groups of 4 dims
        const int qq = t >> 3;      // 16 q groups; rows qq, qq+16, qq+32, (qq+48)
        float4 acc[4];
        #pragma unroll
        for (int j = 0; j < 4; j++) acc[j] = make_float4(0.f, 0.f, 0.f, 0.f);
        const float4* v4 = (const float4*)&v_s[0][0];
        #pragma unroll 7
        for (int k = 0; k < WD; k++) {
            float4 vv = v4[k * 8 + dg];
            #pragma unroll
            for (int j = 0; j < 4; j++) {
                int q = qq + 16 * j;
                if (q < WD) {
                    float s = s_s[q][k];
                    acc[j].x += s * vv.x; acc[j].y += s * vv.y;
                    acc[j].z += s * vv.z; acc[j].w += s * vv.w;
                }
            }
        }
        float* Yb = g_Y + ((size_t)b * NPOS) * EMB + h * HDIM + dg * 4;
        #pragma unroll
        for (int j = 0; j < 4; j++) {
            int q = qq + 16 * j;
            if (q < WD) *(float4*)(Yb + (size_t)pos_s[q] * EMB) = acc[j];
        }
    }
}

// ---------------------------------------------------------------------------
// Kernel 3: out = Y @ proj_w + proj_b  (M=100352, N=256, K=256)
// 128x128 tile, 256 threads, 8x8 microtile (split-4 pattern), BK=16,
// register prefetch double buffering.
// ---------------------------------------------------------------------------
__global__ __launch_bounds__(256) void proj_kernel(
    const float* __restrict__ Wg,
    const float* __restrict__ bg,
    float* __restrict__ out)
{
    const int t  = threadIdx.x;
    const int tx = t & 15;
    const int ty = t >> 4;
    const int n0 = blockIdx.x * 128;
    const int m0 = blockIdx.y * 128;

    __shared__ float As[16][128];
    __shared__ float Bs[16][128];

    float acc[8][8];
    #pragma unroll
    for (int i = 0; i < 8; i++)
        #pragma unroll
        for (int j = 0; j < 8; j++) acc[i][j] = 0.0f;

    const float* Ybase = g_Y + (size_t)m0 * EMB;

    // A-load mapping: f = t*2+i -> m = f>>2, kq = (f&3)*4
    const int amA = (t * 2) >> 2;          // same m for both i (f, f+1 share m when t*2%4<3)
    // (recompute inside loop for clarity)

    float4 pa[2], pb[2];

    auto fetchA = [&](int kt, int i) -> float4 {
        int f = t * 2 + i;
        int m = f >> 2, kq = (f & 3) * 4;
        return *(const float4*)(Ybase + (size_t)m * EMB + kt * 16 + kq);
    };
    auto fetchB = [&](int kt, int i) -> float4 {
        int f = t * 2 + i;
        int kr = f >> 5, c4 = (f & 31) * 4;
        return *(const float4*)(Wg + (size_t)(kt * 16 + kr) * EMB + n0 + c4);
    };
    auto storeA = [&](int i, float4 v) {
        int f = t * 2 + i;
        int m = f >> 2, kq = (f & 3) * 4;
        As[kq + 0][m] = v.x; As[kq + 1][m] = v.y;
        As[kq + 2][m] = v.z; As[kq + 3][m] = v.w;
    };
    auto storeB = [&](int i, float4 v) {
        int f = t * 2 + i;
        int kr = f >> 5, c4 = (f & 31) * 4;
        *(float4*)&Bs[kr][c4] = v;
    };
    (void)amA;

    // initial tile
    storeA(0, fetchA(0, 0)); storeA(1, fetchA(0, 1));
    storeB(0, fetchB(0, 0)); storeB(1, fetchB(0, 1));
    __syncthreads();

    for (int kt = 0; kt < 16; kt++) {
        if (kt < 15) {
            pa[0] = fetchA(kt + 1, 0); pa[1] = fetchA(kt + 1, 1);
            pb[0] = fetchB(kt + 1, 0); pb[1] = fetchB(kt + 1, 1);
        }
        #pragma unroll
        for (int kk = 0; kk < 16; kk++) {
            float4 a0 = *(float4*)&As[kk][ty * 4];
            float4 a1 = *(float4*)&As[kk][ty * 4 + 64];
            float4 b0 = *(float4*)&Bs[kk][tx * 4];
            float4 b1 = *(float4*)&Bs[kk][tx * 4 + 64];
            float ar[8] = {a0.x, a0.y, a0.z, a0.w, a1.x, a1.y, a1.z, a1.w};
            float br[8] = {b0.x, b0.y, b0.z, b0.w, b1.x, b1.y, b1.z, b1.w};
            #pragma unroll
            for (int i = 0; i < 8; i++)
                #pragma unroll
                for (int j = 0; j < 8; j++) acc[i][j] += ar[i] * br[j];
        }
        __syncthreads();
        if (kt < 15) {
            storeA(0, pa[0]); storeA(1, pa[1]);
            storeB(0, pb[0]); storeB(1, pb[1]);
            __syncthreads();
        }
    }

    float4 bb0 = *(const float4*)(bg + n0 + tx * 4);
    float4 bb1 = *(const float4*)(bg + n0 + tx * 4 + 64);
    #pragma unroll
    for (int i = 0; i < 8; i++) {
        int m = m0 + ty * 4 + (i < 4 ? i : 60 + i);   // i>=4 -> +64+(i-4)
        float4 o0, o1;
        o0.x = acc[i][0] + bb0.x; o0.y = acc[i][1] + bb0.y;
        o0.z = acc[i][2] + bb0.z; o0.w = acc[i][3] + bb0.w;
        o1.x = acc[i][4] + bb1.x; o1.y = acc[i][5] + bb1.y;
        o1.z = acc[i][6] + bb1.z; o1.w = acc[i][7] + bb1.w;
        *(float4*)(out + (size_t)m * EMB + n0 + tx * 4)      = o0;
        *(float4*)(out + (size_t)m * EMB + n0 + tx * 4 + 64) = o1;
    }
}

extern "C" void kernel_launch(void* const* d_in, const int* in_sizes, int n_in,
                              void* d_out, int out_size)
{
    const float* x      = (const float*)d_in[0];
    const float* qkv_w  = (const float*)d_in[1];
    const float* qkv_b  = (const float*)d_in[2];
    const float* proj_w = (const float*)d_in[3];
    const float* proj_b = (const float*)d_in[4];
    const float* rpb    = (const float*)d_in[5];
    float* out = (float*)d_out;

    qkv_kernel<<<NBLK, 96>>>(x, qkv_w, qkv_b);
    attn_kernel<<<NBLK, 128>>>(rpb);
    proj_kernel<<<dim3(EMB / 128, (BATCH * NPOS) / 128), 256>>>(proj_w, proj_b, out);
}

// round 4
// speedup vs baseline: 1.5090x; 1.1196x over previous
#include <cuda_runtime.h>
#include <cuda_bf16.h>

#define BATCH 32
#define HW 56
#define EMB 256
#define NHEAD 8
#define HDIM 32
#define NWIN 64
#define WS 7
#define SSH 3
#define WD 49
#define NPOS 3136
#define NBLK (BATCH * NWIN * NHEAD)   // 16384
#define HSL (WD * HDIM)               // 1568 floats per (b,w,h) slice

// Scratch (allocation-free rule: static device arrays)
__device__ float g_Q[(size_t)NBLK * HSL];
__device__ float g_K[(size_t)NBLK * HSL];
__device__ float g_V[(size_t)NBLK * HSL];
__device__ float g_Y[(size_t)BATCH * NPOS * EMB];

// ---------------------------------------------------------------------------
// helpers: token position & shift-mask region for window w, token t
// ---------------------------------------------------------------------------
__device__ __forceinline__ void win_token(int w, int t, int& pos, int& reg)
{
    const int wi = w >> 3, wj = w & 7;
    int a = t / 7, c = t % 7;
    int hh = wi * 7 + a;                 // coordinate in SHIFTED image
    int ww = wj * 7 + c;
    int row = hh + SSH; if (row >= HW) row -= HW;   // original coords
    int col = ww + SSH; if (col >= HW) col -= HW;
    pos = row * HW + col;
    int fh = hh < HW - WS ? 0 : (hh < HW - SSH ? 1 : 2);
    int fw = ww < HW - WS ? 0 : (ww < HW - SSH ? 1 : 2);
    reg = fh * 3 + fw;
}

// ---------------------------------------------------------------------------
// Kernel 1: QKV per window, ALL heads in one block.
// grid = B*NW = 2048 blocks, 256 threads = (head h = t>>5, lane = t&31).
// x window staged once in smem, shared by all heads (no redundant x reads).
// Thread computes Q/K/V column `lane` of head h for all 49 tokens.
// ---------------------------------------------------------------------------
__global__ __launch_bounds__(256) void qkv_kernel(
    const float* __restrict__ x,      // (B,3136,256)
    const float* __restrict__ qkv_w,  // (32,96)
    const float* __restrict__ qkv_b)  // (96,)
{
    const int blk = blockIdx.x;
    const int b   = blk >> 6;
    const int w   = blk & (NWIN - 1);
    const int t   = threadIdx.x;
    const int h   = t >> 5;
    const int ln  = t & 31;

    __shared__ float xs[WD][EMB];     // 49 x 256 = 49 KB
    __shared__ int   pos_s[WD];

    if (t < WD) { int p, r; win_token(w, t, p, r); pos_s[t] = p; }
    __syncthreads();

    // stage x window: 49 rows x 64 float4, coalesced per row
    {
        const float* xb = x + ((size_t)b * NPOS) * EMB;
        for (int i = t; i < WD * 64; i += 256) {
            int tok = i >> 6, c = i & 63;
            ((float4*)&xs[tok][0])[c] =
                ((const float4*)(xb + (size_t)pos_s[tok] * EMB))[c];
        }
    }

    // weight columns (lane, lane+32, lane+64) in registers; reused 49x
    float wq[HDIM], wk[HDIM], wv[HDIM];
    #pragma unroll
    for (int kk = 0; kk < HDIM; kk++) {
        wq[kk] = __ldg(&qkv_w[kk * 96 + ln]);
        wk[kk] = __ldg(&qkv_w[kk * 96 + 32 + ln]);
        wv[kk] = __ldg(&qkv_w[kk * 96 + 64 + ln]);
    }
    const float bq = __ldg(&qkv_b[ln]) * 0.17677669529663688f;  // 1/sqrt(32) in q
    const float bk = __ldg(&qkv_b[32 + ln]);
    const float bv = __ldg(&qkv_b[64 + ln]);
    __syncthreads();

    const size_t hb = (size_t)(blk * NHEAD + h) * HSL + ln;
    float* dq = g_Q + hb;
    float* dk = g_K + hb;
    float* dv = g_V + hb;

    #pragma unroll 7
    for (int tok = 0; tok < WD; tok++) {
        const float4* xr = (const float4*)&xs[tok][h * HDIM];  // broadcast in warp
        float aq = bq, ak = bk, av = bv;
        #pragma unroll
        for (int j = 0; j < 8; j++) {
            float4 xv = xr[j];
            aq += xv.x * wq[j*4+0] + xv.y * wq[j*4+1] + xv.z * wq[j*4+2] + xv.w * wq[j*4+3];
            ak += xv.x * wk[j*4+0] + xv.y * wk[j*4+1] + xv.z * wk[j*4+2] + xv.w * wk[j*4+3];
            av += xv.x * wv[j*4+0] + xv.y * wv[j*4+1] + xv.z * wv[j*4+2] + xv.w * wv[j*4+3];
        }
        aq *= 0.17677669529663688f;   // scale the dot-product part; bias pre-scaled
        // note: bq was pre-scaled, aq started from bq then got unscaled dots added —
        // fix: recompute properly below
        dq[(size_t)tok * HDIM] = aq;
        dk[(size_t)tok * HDIM] = ak;
        dv[(size_t)tok * HDIM] = av;
    }
}

// The scaling above would double-scale bq; to keep it exact we instead start q
// from the raw bias and scale the whole thing once. (Correct version follows —
// the kernel actually compiled is qkv_kernel_fixed.)
__global__ __launch_bounds__(256) void qkv_kernel_fixed(
    const float* __restrict__ x,
    const float* __restrict__ qkv_w,
    const float* __restrict__ qkv_b)
{
    const int blk = blockIdx.x;
    const int b   = blk >> 6;
    const int w   = blk & (NWIN - 1);
    const int t   = threadIdx.x;
    const int h   = t >> 5;
    const int ln  = t & 31;

    __shared__ float xs[WD][EMB];
    __shared__ int   pos_s[WD];

    if (t < WD) { int p, r; win_token(w, t, p, r); pos_s[t] = p; }
    __syncthreads();

    {
        const float* xb = x + ((size_t)b * NPOS) * EMB;
        for (int i = t; i < WD * 64; i += 256) {
            int tok = i >> 6, c = i & 63;
            ((float4*)&xs[tok][0])[c] =
                ((const float4*)(xb + (size_t)pos_s[tok] * EMB))[c];
        }
    }

    float wq[HDIM], wk[HDIM], wv[HDIM];
    #pragma unroll
    for (int kk = 0; kk < HDIM; kk++) {
        wq[kk] = __ldg(&qkv_w[kk * 96 + ln]);
        wk[kk] = __ldg(&qkv_w[kk * 96 + 32 + ln]);
        wv[kk] = __ldg(&qkv_w[kk * 96 + 64 + ln]);
    }
    const float bq = __ldg(&qkv_b[ln]);
    const float bk = __ldg(&qkv_b[32 + ln]);
    const float bv = __ldg(&qkv_b[64 + ln]);
    __syncthreads();

    const size_t hb = (size_t)(blk * NHEAD + h) * HSL + ln;
    float* dq = g_Q + hb;
    float* dk = g_K + hb;
    float* dv = g_V + hb;

    #pragma unroll 7
    for (int tok = 0; tok < WD; tok++) {
        const float4* xr = (const float4*)&xs[tok][h * HDIM];
        float aq = bq, ak = bk, av = bv;
        #pragma unroll
        for (int j = 0; j < 8; j++) {
            float4 xv = xr[j];
            aq += xv.x * wq[j*4+0] + xv.y * wq[j*4+1] + xv.z * wq[j*4+2] + xv.w * wq[j*4+3];
            ak += xv.x * wk[j*4+0] + xv.y * wk[j*4+1] + xv.z * wk[j*4+2] + xv.w * wk[j*4+3];
            av += xv.x * wv[j*4+0] + xv.y * wv[j*4+1] + xv.z * wv[j*4+2] + xv.w * wv[j*4+3];
        }
        dq[(size_t)tok * HDIM] = aq * 0.17677669529663688f;
        dk[(size_t)tok * HDIM] = ak;
        dv[(size_t)tok * HDIM] = av;
    }
}

// ---------------------------------------------------------------------------
// Kernel 2: windowed attention per (b,w,h). 128 threads. (unchanged)
// ---------------------------------------------------------------------------
__global__ __launch_bounds__(128) void attn_kernel(
    const float* __restrict__ rpb)    // (169, 8)
{
    const int blk = blockIdx.x;
    const int h   = blk & (NHEAD - 1);
    const int w   = (blk >> 3) & (NWIN - 1);
    const int b   = blk >> 9;
    const int t   = threadIdx.x;

    __shared__ float k_s[WD][HDIM];
    __shared__ float v_s[WD][HDIM];
    __shared__ float s_s[WD][WD];
    __shared__ float rpb_s[169];
    __shared__ int   pos_s[WD];
    __shared__ int   reg_s[WD];

    if (t < WD) { int p, r; win_token(w, t, p, r); pos_s[t] = p; reg_s[t] = r; }
    for (int i = t; i < 169; i += 128) rpb_s[i] = rpb[i * NHEAD + h];

    const size_t base = (size_t)blk * HSL;
    {
        const float4* gk = (const float4*)(g_K + base);
        const float4* gv = (const float4*)(g_V + base);
        float4* ks4 = (float4*)&k_s[0][0];
        float4* vs4 = (float4*)&v_s[0][0];
        for (int i = t; i < HSL / 4; i += 128) { ks4[i] = gk[i]; vs4[i] = gv[i]; }
    }
    __syncthreads();

    if (t < 2 * WD) {
        const int q = t >> 1, half = t & 1;
        float4 qreg[8];
        const float4* gq = (const float4*)(g_Q + base + (size_t)q * HDIM);
        #pragma unroll
        for (int j = 0; j < 8; j++) qreg[j] = gq[j];
        const int aq = q / 7, bq = q % 7;
        const int rq = reg_s[q];
        const int k0 = half * 25, k1 = half ? WD : 25;
        for (int k = k0; k < k1; k++) {
            const float4* kr = (const float4*)&k_s[k][0];
            float acc = 0.0f;
            #pragma unroll
            for (int j = 0; j < 8; j++) {
                float4 kv = kr[j];
                acc += qreg[j].x * kv.x + qreg[j].y * kv.y
                     + qreg[j].z * kv.z + qreg[j].w * kv.w;
            }
            int ak = k / 7, bk = k % 7;
            acc += rpb_s[(aq - ak + WS - 1) * (2 * WS - 1) + (bq - bk + WS - 1)];
            if (reg_s[k] != rq) acc -= 100.0f;
            s_s[q][k] = acc;
        }
    }
    __syncthreads();

    {
        const int warp = t >> 5, lane = t & 31;
        for (int r = warp; r < WD; r += 4) {
            float v0 = s_s[r][lane];
            float v1 = (lane + 32 < WD) ? s_s[r][lane + 32] : -1e30f;
            float m = fmaxf(v0, v1);
            #pragma unroll
            for (int o = 16; o; o >>= 1) m = fmaxf(m, __shfl_xor_sync(~0u, m, o));
            float e0 = __expf(v0 - m);
            float e1 = (lane + 32 < WD) ? __expf(v1 - m) : 0.0f;
            float s = e0 + e1;
            #pragma unroll
            for (int o = 16; o; o >>= 1) s += __shfl_xor_sync(~0u, s, o);
            float inv = 1.0f / s;
            s_s[r][lane] = e0 * inv;
            if (lane + 32 < WD) s_s[r][lane + 32] = e1 * inv;
        }
    }
    __syncthreads();

    {
        const int dg = t & 7;
        const int qq = t >> 3;
        float4 acc[4];
        #pragma unroll
        for (int j = 0; j < 4; j++) acc[j] = make_float4(0.f, 0.f, 0.f, 0.f);
        const float4* v4 = (const float4*)&v_s[0][0];
        #pragma unroll 7
        for (int k = 0; k < WD; k++) {
            float4 vv = v4[k * 8 + dg];
            #pragma unroll
            for (int j = 0; j < 4; j++) {
                int q = qq + 16 * j;
                if (q < WD) {
                    float s = s_s[q][k];
                    acc[j].x += s * vv.x; acc[j].y += s * vv.y;
                    acc[j].z += s * vv.z; acc[j].w += s * vv.w;
                }
            }
        }
        float* Yb = g_Y + ((size_t)b * NPOS) * EMB + h * HDIM + dg * 4;
        #pragma unroll
        for (int j = 0; j < 4; j++) {
            int q = qq + 16 * j;
            if (q < WD) *(float4*)(Yb + (size_t)pos_s[q] * EMB) = acc[j];
        }
    }
}

// ---------------------------------------------------------------------------
// Kernel 3: out = Y @ proj_w + proj_b  (M=100352, N=256, K=256) (unchanged)
// ---------------------------------------------------------------------------
__global__ __launch_bounds__(256) void proj_kernel(
    const float* __restrict__ Wg,
    const float* __restrict__ bg,
    float* __restrict__ out)
{
    const int t  = threadIdx.x;
    const int tx = t & 15;
    const int ty = t >> 4;
    const int n0 = blockIdx.x * 128;
    const int m0 = blockIdx.y * 128;

    __shared__ float As[16][128];
    __shared__ float Bs[16][128];

    float acc[8][8];
    #pragma unroll
    for (int i = 0; i < 8; i++)
        #pragma unroll
        for (int j = 0; j < 8; j++) acc[i][j] = 0.0f;

    const float* Ybase = g_Y + (size_t)m0 * EMB;

    float4 pa[2], pb[2];

    auto fetchA = [&](int kt, int i) -> float4 {
        int f = t * 2 + i;
        int m = f >> 2, kq = (f & 3) * 4;
        return *(const float4*)(Ybase + (size_t)m * EMB + kt * 16 + kq);
    };
    auto fetchB = [&](int kt, int i) -> float4 {
        int f = t * 2 + i;
        int kr = f >> 5, c4 = (f & 31) * 4;
        return *(const float4*)(Wg + (size_t)(kt * 16 + kr) * EMB + n0 + c4);
    };
    auto storeA = [&](int i, float4 v) {
        int f = t * 2 + i;
        int m = f >> 2, kq = (f & 3) * 4;
        As[kq + 0][m] = v.x; As[kq + 1][m] = v.y;
        As[kq + 2][m] = v.z; As[kq + 3][m] = v.w;
    };
    auto storeB = [&](int i, float4 v) {
        int f = t * 2 + i;
        int kr = f >> 5, c4 = (f & 31) * 4;
        *(float4*)&Bs[kr][c4] = v;
    };

    storeA(0, fetchA(0, 0)); storeA(1, fetchA(0, 1));
    storeB(0, fetchB(0, 0)); storeB(1, fetchB(0, 1));
    __syncthreads();

    for (int kt = 0; kt < 16; kt++) {
        if (kt < 15) {
            pa[0] = fetchA(kt + 1, 0); pa[1] = fetchA(kt + 1, 1);
            pb[0] = fetchB(kt + 1, 0); pb[1] = fetchB(kt + 1, 1);
        }
        #pragma unroll
        for (int kk = 0; kk < 16; kk++) {
            float4 a0 = *(float4*)&As[kk][ty * 4];
            float4 a1 = *(float4*)&As[kk][ty * 4 + 64];
            float4 b0 = *(float4*)&Bs[kk][tx * 4];
            float4 b1 = *(float4*)&Bs[kk][tx * 4 + 64];
            float ar[8] = {a0.x, a0.y, a0.z, a0.w, a1.x, a1.y, a1.z, a1.w};
            float br[8] = {b0.x, b0.y, b0.z, b0.w, b1.x, b1.y, b1.z, b1.w};
            #pragma unroll
            for (int i = 0; i < 8; i++)
                #pragma unroll
                for (int j = 0; j < 8; j++) acc[i][j] += ar[i] * br[j];
        }
        __syncthreads();
        if (kt < 15) {
            storeA(0, pa[0]); storeA(1, pa[1]);
            storeB(0, pb[0]); storeB(1, pb[1]);
            __syncthreads();
        }
    }

    float4 bb0 = *(const float4*)(bg + n0 + tx * 4);
    float4 bb1 = *(const float4*)(bg + n0 + tx * 4 + 64);
    #pragma unroll
    for (int i = 0; i < 8; i++) {
        int m = m0 + ty * 4 + (i < 4 ? i : 60 + i);
        float4 o0, o1;
        o0.x = acc[i][0] + bb0.x; o0.y = acc[i][1] + bb0.y;
        o0.z = acc[i][2] + bb0.z; o0.w = acc[i][3] + bb0.w;
        o1.x = acc[i][4] + bb1.x; o1.y = acc[i][5] + bb1.y;
        o1.z = acc[i][6] + bb1.z; o1.w = acc[i][7] + bb1.w;
        *(float4*)(out + (size_t)m * EMB + n0 + tx * 4)      = o0;
        *(float4*)(out + (size_t)m * EMB + n0 + tx * 4 + 64) = o1;
    }
}

extern "C" void kernel_launch(void* const* d_in, const int* in_sizes, int n_in,
                              void* d_out, int out_size)
{
    const float* x      = (const float*)d_in[0];
    const float* qkv_w  = (const float*)d_in[1];
    const float* qkv_b  = (const float*)d_in[2];
    const float* proj_w = (const float*)d_in[3];
    const float* proj_b = (const float*)d_in[4];
    const float* rpb    = (const float*)d_in[5];
    float* out = (float*)d_out;

    qkv_kernel_fixed<<<BATCH * NWIN, 256>>>(x, qkv_w, qkv_b);
    attn_kernel<<<NBLK, 128>>>(rpb);
    proj_kernel<<<dim3(EMB / 128, (BATCH * NPOS) / 128), 256>>>(proj_w, proj_b, out);
}